// round 5
// baseline (speedup 1.0000x reference)
#include <cuda_runtime.h>
#include <math.h>

#define BATCH 8

// ---------------- scratch (device globals; no runtime allocation) ----------------
__device__ __align__(256) float g_e1[BATCH*256*256*16];
__device__ __align__(256) float g_e2[BATCH*128*128*16];
__device__ __align__(256) float g_e3[BATCH*64*64*32];
__device__ __align__(256) float g_dA[BATCH*256*256*64];
__device__ __align__(256) float g_dB[BATCH*256*256*64];
__device__ __align__(256) float g_mA[BATCH*256*256];
__device__ __align__(256) float g_mB[BATCH*256*256];
__device__ double g_part[4096];

__device__ __forceinline__ float gelu_f(float x) {
    float t = tanhf(0.7978845608028654f * (x + 0.044715f * x * x * x));
    return 0.5f * x * (1.0f + t);
}

// ---------------- encoder layer 1: conv 1->16, s1, SAME(pad1) + chan-norm + gelu ----
__global__ __launch_bounds__(256) void k_trio1(
    const float* __restrict__ img, const float* __restrict__ w,
    const float* __restrict__ bias, float* __restrict__ out)
{
    __shared__ float ws[144];
    __shared__ float ins[18][19];
    const int tid = threadIdx.x, bb = blockIdx.z;
    const int y0 = blockIdx.y * 16, x0 = blockIdx.x * 16;
    if (tid < 144) ws[tid] = w[tid];
    for (int idx = tid; idx < 18 * 18; idx += 256) {
        int r = idx / 18, c = idx % 18;
        int gy = y0 + r - 1, gx = x0 + c - 1;
        float v = 0.f;
        if (gy >= 0 && gy < 256 && gx >= 0 && gx < 256)
            v = img[((size_t)bb * 256 + gy) * 256 + gx];
        ins[r][c] = v;
    }
    __syncthreads();
    const int py = tid / 16, px = tid % 16;
    float acc[16];
#pragma unroll
    for (int j = 0; j < 16; j++) acc[j] = __ldg(&bias[j]);
#pragma unroll
    for (int ky = 0; ky < 3; ky++)
#pragma unroll
        for (int kx = 0; kx < 3; kx++) {
            float v = ins[py + ky][px + kx];
            const float* wr = &ws[(ky * 3 + kx) * 16];
#pragma unroll
            for (int j = 0; j < 16; j++) acc[j] += wr[j] * v;
        }
    float s = 0.f;
#pragma unroll
    for (int j = 0; j < 16; j++) s += acc[j];
    float mu = s * (1.0f / 16.0f);
    float ss = 0.f;
#pragma unroll
    for (int j = 0; j < 16; j++) { float d = acc[j] - mu; ss += d * d; }
    float inv = rsqrtf(ss * (1.0f / 16.0f) + 1e-6f);
    float* ob = &out[(((size_t)bb * 256 + y0 + py) * 256 + x0 + px) * 16];
#pragma unroll
    for (int j4 = 0; j4 < 4; j4++) {
        float4 o;
        o.x = gelu_f((acc[4 * j4 + 0] - mu) * inv);
        o.y = gelu_f((acc[4 * j4 + 1] - mu) * inv);
        o.z = gelu_f((acc[4 * j4 + 2] - mu) * inv);
        o.w = gelu_f((acc[4 * j4 + 3] - mu) * inv);
        reinterpret_cast<float4*>(ob)[j4] = o;
    }
}

// ---------------- generic stride-2 Conv_trio (SAME: pad lo=0,hi=1 -> in = 2*o + k) --------
template<int CIN, int COUT, int TH, int TW, int CG>
__global__ __launch_bounds__(TH* TW* CG) void k_trio_s2(
    const float* __restrict__ in, int inH, int inW,
    const float* __restrict__ w, const float* __restrict__ bias,
    float* __restrict__ out, int outH, int outW)
{
    constexpr int ITH = 2 * TH + 1, ITW = 2 * TW + 1, ICP = ITW + 1;
    constexpr int NW = 9 * CIN * COUT;
    constexpr int NPX = TH * TW;
    constexpr int NT = NPX * CG;
    constexpr int COG = COUT / CG;
    extern __shared__ float sm[];
    float* ws = sm;
    float* ins = sm + NW;
    float* red = ins + CIN * ITH * ICP;

    const int tid = threadIdx.x, bb = blockIdx.z;
    const int y0 = blockIdx.y * TH, x0 = blockIdx.x * TW;

    for (int i = tid; i < NW / 4; i += NT)
        reinterpret_cast<float4*>(ws)[i] = reinterpret_cast<const float4*>(w)[i];
    for (int idx = tid; idx < ITH * ITW * (CIN / 4); idx += NT) {
        int f = idx % (CIN / 4);
        int pos = idx / (CIN / 4);
        int r = pos / ITW, c = pos % ITW;
        int gy = 2 * y0 + r, gx = 2 * x0 + c;
        float4 v = make_float4(0.f, 0.f, 0.f, 0.f);
        if (gy < inH && gx < inW)
            v = *reinterpret_cast<const float4*>(&in[((size_t)(bb * inH + gy) * inW + gx) * CIN + 4 * f]);
        float* ib = &ins[r * ICP + c];
        int ci = 4 * f;
        ib[(ci + 0) * ITH * ICP] = v.x;
        ib[(ci + 1) * ITH * ICP] = v.y;
        ib[(ci + 2) * ITH * ICP] = v.z;
        ib[(ci + 3) * ITH * ICP] = v.w;
    }
    __syncthreads();

    const int p = tid % NPX, g = tid / NPX;
    const int py = p / TW, px = p % TW;
    float acc[COG];
#pragma unroll
    for (int j = 0; j < COG; j++) acc[j] = __ldg(&bias[g * COG + j]);

#pragma unroll
    for (int ky = 0; ky < 3; ky++)
#pragma unroll
        for (int kx = 0; kx < 3; kx++) {
            const float* ib = &ins[(2 * py + ky) * ICP + (2 * px + kx)];
            const float* wb = &ws[(ky * 3 + kx) * CIN * COUT + g * COG];
#pragma unroll 2
            for (int ci = 0; ci < CIN; ci++) {
                float v = ib[ci * ITH * ICP];
                const float4* wr = reinterpret_cast<const float4*>(&wb[ci * COUT]);
#pragma unroll
                for (int j4 = 0; j4 < COG / 4; j4++) {
                    float4 wv = wr[j4];
                    acc[4 * j4 + 0] += wv.x * v;
                    acc[4 * j4 + 1] += wv.y * v;
                    acc[4 * j4 + 2] += wv.z * v;
                    acc[4 * j4 + 3] += wv.w * v;
                }
            }
        }

    float mu, var;
    if (CG == 1) {
        float s = 0.f;
#pragma unroll
        for (int j = 0; j < COG; j++) s += acc[j];
        mu = s / (float)COUT;
        float ss = 0.f;
#pragma unroll
        for (int j = 0; j < COG; j++) { float d = acc[j] - mu; ss += d * d; }
        var = ss / (float)COUT;
    } else {
        float s = 0.f;
#pragma unroll
        for (int j = 0; j < COG; j++) s += acc[j];
        red[p * CG + g] = s;
        __syncthreads();
        float msum = 0.f;
#pragma unroll
        for (int k = 0; k < CG; k++) msum += red[p * CG + k];
        mu = msum / (float)COUT;
        float ss = 0.f;
#pragma unroll
        for (int j = 0; j < COG; j++) { float d = acc[j] - mu; ss += d * d; }
        __syncthreads();
        red[p * CG + g] = ss;
        __syncthreads();
        float vsum = 0.f;
#pragma unroll
        for (int k = 0; k < CG; k++) vsum += red[p * CG + k];
        var = vsum / (float)COUT;
    }
    float inv = rsqrtf(var + 1e-6f);
    const int y = y0 + py, x = x0 + px;
    float* ob = &out[((size_t)(bb * outH + y) * outW + x) * COUT + g * COG];
#pragma unroll
    for (int j4 = 0; j4 < COG / 4; j4++) {
        float4 o;
        o.x = gelu_f((acc[4 * j4 + 0] - mu) * inv);
        o.y = gelu_f((acc[4 * j4 + 1] - mu) * inv);
        o.z = gelu_f((acc[4 * j4 + 2] - mu) * inv);
        o.w = gelu_f((acc[4 * j4 + 3] - mu) * inv);
        reinterpret_cast<float4*>(ob)[j4] = o;
    }
}

// ---------------- conv_transpose 64->64 (3x3, s2 along DIM, SAME) + gelu -------------------
// out[2m] = w[0]*x[m-1] + w[2]*x[m]; out[2m+1] = w[1]*x[m] along the strided dim;
// centered 3-tap along the unstrided dim. No kernel flip (transpose_kernel=False).
// Processes NB_PER_BLOCK batch images per block to amortize the 147KB weight staging.
template<int DIM>
__global__ __launch_bounds__(256) void k_upconv(
    const float* __restrict__ in, int inH, int inW,
    const float* __restrict__ w, const float* __restrict__ bias,
    float* __restrict__ out)
{
    extern __shared__ float sm[];
    float* ws = sm;              // 9*64*64 = 36864 floats
    float* ins = sm + 36864;     // 64 * 10 * 11 = 7040 floats
    const int tid = threadIdx.x;
    const int outH = (DIM == 0) ? 2 * inH : inH;
    const int outW = (DIM == 0) ? inW : 2 * inW;
    const int S0 = (DIM == 0) ? (int)blockIdx.y * 8 : (int)blockIdx.x * 8; // strided base
    const int U0 = (DIM == 0) ? (int)blockIdx.x * 8 : (int)blockIdx.y * 8; // unstrided base
    const int r0 = ((DIM == 0) ? S0 : U0) - 1;
    const int c0 = ((DIM == 0) ? U0 : S0) - 1;

    for (int i = tid; i < 9216; i += 256)
        reinterpret_cast<float4*>(ws)[i] = reinterpret_cast<const float4*>(w)[i];

    const int p = tid & 63, g = tid >> 6;
    const int q = p >> 3, u = p & 7;

    for (int bb = 2 * blockIdx.z; bb < 2 * blockIdx.z + 2; bb++) {
        for (int idx = tid; idx < 10 * 10 * 16; idx += 256) {
            int f = idx & 15;
            int pos = idx >> 4;
            int r = pos / 10, c = pos % 10;
            int gy = r0 + r, gx = c0 + c;
            float4 v = make_float4(0.f, 0.f, 0.f, 0.f);
            if (gy >= 0 && gy < inH && gx >= 0 && gx < inW)
                v = *reinterpret_cast<const float4*>(&in[((size_t)(bb * inH + gy) * inW + gx) * 64 + 4 * f]);
            float* ib = &ins[r * 11 + c];
            ib[(4 * f + 0) * 110] = v.x;
            ib[(4 * f + 1) * 110] = v.y;
            ib[(4 * f + 2) * 110] = v.z;
            ib[(4 * f + 3) * 110] = v.w;
        }
        __syncthreads();

        float aE[16], aO[16];
#pragma unroll
        for (int j = 0; j < 16; j++) {
            float bv = __ldg(&bias[g * 16 + j]);
            aE[j] = bv; aO[j] = bv;
        }

#pragma unroll 2
        for (int ci = 0; ci < 64; ci++) {
            const float* ib = &ins[ci * 110];
#pragma unroll
            for (int k = 0; k < 3; k++) {
                float v0, v1;
                int t0, t1, t2;
                if (DIM == 0) {
                    v0 = ib[q * 11 + u + k];
                    v1 = ib[(q + 1) * 11 + u + k];
                    t0 = 0 * 3 + k; t1 = 1 * 3 + k; t2 = 2 * 3 + k;
                } else {
                    v0 = ib[(u + k) * 11 + q];
                    v1 = ib[(u + k) * 11 + q + 1];
                    t0 = k * 3 + 0; t1 = k * 3 + 1; t2 = k * 3 + 2;
                }
                const float4* w0 = reinterpret_cast<const float4*>(&ws[(t0 * 64 + ci) * 64 + g * 16]);
                const float4* w1 = reinterpret_cast<const float4*>(&ws[(t1 * 64 + ci) * 64 + g * 16]);
                const float4* w2 = reinterpret_cast<const float4*>(&ws[(t2 * 64 + ci) * 64 + g * 16]);
#pragma unroll
                for (int j4 = 0; j4 < 4; j4++) {
                    float4 a = w0[j4], b2 = w2[j4], c1 = w1[j4];
                    aE[4 * j4 + 0] += a.x * v0 + b2.x * v1;
                    aE[4 * j4 + 1] += a.y * v0 + b2.y * v1;
                    aE[4 * j4 + 2] += a.z * v0 + b2.z * v1;
                    aE[4 * j4 + 3] += a.w * v0 + b2.w * v1;
                    aO[4 * j4 + 0] += c1.x * v1;
                    aO[4 * j4 + 1] += c1.y * v1;
                    aO[4 * j4 + 2] += c1.z * v1;
                    aO[4 * j4 + 3] += c1.w * v1;
                }
            }
        }

        int yE, yO, xE, xO;
        if (DIM == 0) { yE = 2 * (S0 + q); yO = yE + 1; xE = U0 + u; xO = xE; }
        else { yE = U0 + u; yO = yE; xE = 2 * (S0 + q); xO = xE + 1; }
        float* oE = &out[((size_t)(bb * outH + yE) * outW + xE) * 64 + g * 16];
        float* oO = &out[((size_t)(bb * outH + yO) * outW + xO) * 64 + g * 16];
#pragma unroll
        for (int j4 = 0; j4 < 4; j4++) {
            float4 oe, oo;
            oe.x = gelu_f(aE[4 * j4 + 0]); oe.y = gelu_f(aE[4 * j4 + 1]);
            oe.z = gelu_f(aE[4 * j4 + 2]); oe.w = gelu_f(aE[4 * j4 + 3]);
            oo.x = gelu_f(aO[4 * j4 + 0]); oo.y = gelu_f(aO[4 * j4 + 1]);
            oo.z = gelu_f(aO[4 * j4 + 2]); oo.w = gelu_f(aO[4 * j4 + 3]);
            reinterpret_cast<float4*>(oE)[j4] = oe;
            reinterpret_cast<float4*>(oO)[j4] = oo;
        }
        __syncthreads();   // protect ins before next batch image refill
    }
}

// ---------------- fused mask conv(64->4) + softmax + loss + mask update -------------------
__global__ __launch_bounds__(256) void k_mask(
    const float* __restrict__ dec, int h, int w,
    const float* __restrict__ mw, const float* __restrict__ mb,
    const float* __restrict__ img,
    const float* __restrict__ mprev, float* __restrict__ mnext,
    int dim, int ry, int rx, double lw, double* __restrict__ part)
{
    __shared__ float ws[2304];            // 9*64*4
    __shared__ float ins[16 * 342];       // 16ch chunk, 18x19 tile
    __shared__ float red[8];
    const int tid = threadIdx.x, bb = blockIdx.z;
    const int y0 = blockIdx.y * 16, x0 = blockIdx.x * 16;
    for (int i = tid; i < 576; i += 256)
        reinterpret_cast<float4*>(ws)[i] = reinterpret_cast<const float4*>(mw)[i];

    const int py = tid / 16, px = tid % 16;
    float z0 = __ldg(&mb[0]), z1 = __ldg(&mb[1]), z2 = __ldg(&mb[2]), z3 = __ldg(&mb[3]);

    for (int ch = 0; ch < 4; ch++) {
        __syncthreads();
        for (int idx = tid; idx < 18 * 18 * 4; idx += 256) {
            int f = idx & 3, pos = idx >> 2;
            int r = pos / 18, c = pos % 18;
            int gy = y0 + r - 1, gx = x0 + c - 1;
            float4 v = make_float4(0.f, 0.f, 0.f, 0.f);
            if (gy >= 0 && gy < h && gx >= 0 && gx < w)
                v = *reinterpret_cast<const float4*>(
                    &dec[((size_t)(bb * h + gy) * w + gx) * 64 + ch * 16 + 4 * f]);
            float* ib = &ins[r * 19 + c];
            ib[(4 * f + 0) * 342] = v.x;
            ib[(4 * f + 1) * 342] = v.y;
            ib[(4 * f + 2) * 342] = v.z;
            ib[(4 * f + 3) * 342] = v.w;
        }
        __syncthreads();
#pragma unroll
        for (int ky = 0; ky < 3; ky++)
#pragma unroll
            for (int kx = 0; kx < 3; kx++) {
                const float* ib = &ins[(py + ky) * 19 + (px + kx)];
                const float4* wt = reinterpret_cast<const float4*>(&ws[(ky * 3 + kx) * 256 + ch * 64]);
#pragma unroll
                for (int cl = 0; cl < 16; cl++) {
                    float v = ib[cl * 342];
                    float4 wv = wt[cl];
                    z0 += wv.x * v; z1 += wv.y * v; z2 += wv.z * v; z3 += wv.w * v;
                }
            }
    }

    float m = fmaxf(fmaxf(z0, z1), fmaxf(z2, z3));
    float e0 = expf(z0 - m), e1 = expf(z1 - m), e2 = expf(z2 - m), e3 = expf(z3 - m);
    float inv = 1.0f / (e0 + e1 + e2 + e3);
    float p0 = e0 * inv, p1 = e1 * inv, p2 = e2 * inv, p3 = e3 * inv;
    float pm = p1 + 2.f * p2 + 3.f * p3;
    float ent = -(p0 * logf(p0 + 1e-8f) + p1 * logf(p1 + 1e-8f) +
                  p2 * logf(p2 + 1e-8f) + p3 * logf(p3 + 1e-8f));
    const int y = y0 + py, x = x0 + px;
    float s = 0.f;
    for (int iy = 0; iy < ry; iy++) {
        const float* ip = &img[((size_t)bb * 256 + (size_t)y * ry + iy) * 256 + (size_t)x * rx];
        for (int ix = 0; ix < rx; ix++) s += ip[ix];
    }
    float ds = s / (float)(ry * rx);
    float diff = pm * (1.0f / 3.0f) - ds;
    float contrib = ent + diff * diff;

    // masks: repeat along dim then add 0.25 * pm
    int ph = (dim == 0) ? h / 2 : h;
    int pw = (dim == 1) ? w / 2 : w;
    int pyv = (dim == 0) ? (y >> 1) : y;
    int pxv = (dim == 1) ? (x >> 1) : x;
    mnext[((size_t)bb * h + y) * w + x] =
        mprev[((size_t)bb * ph + pyv) * pw + pxv] + 0.25f * pm;

    // deterministic per-block partial
#pragma unroll
    for (int off = 16; off; off >>= 1)
        contrib += __shfl_down_sync(0xffffffffu, contrib, off);
    if ((tid & 31) == 0) red[tid >> 5] = contrib;
    __syncthreads();
    if (tid == 0) {
        float bs = 0.f;
#pragma unroll
        for (int k = 0; k < 8; k++) bs += red[k];
        int bid = ((int)blockIdx.z * gridDim.y + blockIdx.y) * gridDim.x + blockIdx.x;
        part[bid] = lw * (double)bs;
    }
}

// ---------------- fixed-order loss reduction (deterministic) ----------------
__global__ __launch_bounds__(1024) void k_reduce_loss(float* __restrict__ out, int n)
{
    __shared__ double smd[32];
    double s = 0.0;
    for (int i = threadIdx.x; i < n; i += 1024) s += g_part[i];
#pragma unroll
    for (int o = 16; o; o >>= 1) s += __shfl_down_sync(0xffffffffu, s, o);
    if ((threadIdx.x & 31) == 0) smd[threadIdx.x >> 5] = s;
    __syncthreads();
    if (threadIdx.x < 32) {
        double v = smd[threadIdx.x];
#pragma unroll
        for (int o = 16; o; o >>= 1) v += __shfl_down_sync(0xffffffffu, v, o);
        if (threadIdx.x == 0) out[0] = (float)v;
    }
}

// ---------------- host launcher ----------------
extern "C" void kernel_launch(void* const* d_in, const int* in_sizes, int n_in,
                              void* d_out, int out_size) {
    const float* img    = (const float*)d_in[0];
    const float* w1     = (const float*)d_in[2];
    const float* b1     = (const float*)d_in[3];
    const float* w2     = (const float*)d_in[4];
    const float* b2     = (const float*)d_in[5];
    const float* w3     = (const float*)d_in[6];
    const float* b3     = (const float*)d_in[7];
    const float* w4     = (const float*)d_in[8];
    const float* b4     = (const float*)d_in[9];
    const float* up_w   = (const float*)d_in[10];
    const float* up_b   = (const float*)d_in[11];
    const float* mask_w = (const float*)d_in[12];
    const float* mask_b = (const float*)d_in[13];
    const float* masks0 = (const float*)d_in[14];
    float* out = (float*)d_out;

    float *e1, *e2, *e3, *dA, *dB, *mA, *mB;
    double* part;
    cudaGetSymbolAddress((void**)&e1, g_e1);
    cudaGetSymbolAddress((void**)&e2, g_e2);
    cudaGetSymbolAddress((void**)&e3, g_e3);
    cudaGetSymbolAddress((void**)&dA, g_dA);
    cudaGetSymbolAddress((void**)&dB, g_dB);
    cudaGetSymbolAddress((void**)&mA, g_mA);
    cudaGetSymbolAddress((void**)&mB, g_mB);
    cudaGetSymbolAddress((void**)&part, g_part);

    cudaFuncSetAttribute(k_trio_s2<16,16,16,16,1>, cudaFuncAttributeMaxDynamicSharedMemorySize, 82048);
    cudaFuncSetAttribute(k_trio_s2<16,32,16,16,1>, cudaFuncAttributeMaxDynamicSharedMemorySize, 91264);
    cudaFuncSetAttribute(k_trio_s2<32,64,8,8,4>,   cudaFuncAttributeMaxDynamicSharedMemorySize, 113920);
    cudaFuncSetAttribute(k_upconv<0>, cudaFuncAttributeMaxDynamicSharedMemorySize, 175616);
    cudaFuncSetAttribute(k_upconv<1>, cudaFuncAttributeMaxDynamicSharedMemorySize, 175616);

    // encoder
    k_trio1<<<dim3(16, 16, BATCH), 256>>>(img, w1, b1, e1);
    k_trio_s2<16,16,16,16,1><<<dim3(8, 8, BATCH), 256, 82048>>>(e1, 256, 256, w2, b2, e2, 128, 128);
    k_trio_s2<16,32,16,16,1><<<dim3(4, 4, BATCH), 256, 91264>>>(e2, 128, 128, w3, b3, e3, 64, 64);
    k_trio_s2<32,64,8,8,4><<<dim3(4, 4, BATCH), 256, 113920>>>(e3, 64, 64, w4, b4, dA, 32, 32);

    // decoder steps
    const int inHs[6] = {32, 64, 64, 128, 128, 256};
    const int inWs[6] = {32, 32, 64, 64, 128, 128};
    const double LW[6] = {0.1, 0.1, 0.5, 0.5, 1.0, 1.0};
    const int poff[6] = {0, 64, 192, 448, 960, 1984};

    const float* dsrc = dA;
    float* ddst = dB;
    const float* mprev = masks0;
    float* mbufs[2] = {mA, mB};

    for (int i = 0; i < 6; i++) {
        int dim = i & 1;
        int inH = inHs[i], inW = inWs[i];
        int h = (dim == 0) ? 2 * inH : inH;
        int w = (dim == 0) ? inW : 2 * inW;
        dim3 gup(inW / 8, inH / 8, BATCH / 2);   // 2 batch images per block
        if (dim == 0)
            k_upconv<0><<<gup, 256, 175616>>>(dsrc, inH, inW, up_w, up_b, ddst);
        else
            k_upconv<1><<<gup, 256, 175616>>>(dsrc, inH, inW, up_w, up_b, ddst);

        float* mnext = (i == 5) ? (out + 1) : mbufs[i & 1];
        double lw = LW[i] / (double)(BATCH * h * w);
        dim3 gm(w / 16, h / 16, BATCH);
        k_mask<<<gm, 256>>>(ddst, h, w, mask_w, mask_b, img, mprev, mnext,
                            dim, 256 / h, 256 / w, lw, part + poff[i]);

        mprev = mnext;
        const float* t = dsrc; dsrc = ddst; ddst = (float*)t;
    }

    k_reduce_loss<<<1, 1024>>>(out, 4032);
}